// round 14
// baseline (speedup 1.0000x reference)
#include <cuda_runtime.h>
#include <cstdint>

// MaxUnpooling2D: updates [16,64,64,256] f32, mask [16,64,64,256] i32 (flat idx
// into [16,128,128,256]), out [16,128,128,256] f32.
//
// Row-split scatter (best-scoring structure: 63.68/64.00us harness across two
// samples; kernel plateau 59.1-59.7us, DRAM ~71% = mixed-R:W stream ceiling).
//
// Each pooled cell targets exactly one slot of its private 2x2 window -> no
// duplicate indices -> plain stores; zero-fill fused. One thread = 4 channels
// x 1 window row (ry in {0,1}): 2x16B loads + 2x16B stores 1KB apart in a
// single output row; warp accesses are fully coalesced 512B transactions.
//
// R14 = R13 retry (R13 bench hit a broker-side container failure, same as
// rounds 0/3). Single change vs R8: block 256 -> 128 (65536 blocks, ~55
// waves at 64 warps/SM). The two best harness scores are the only fine-grid
// variants; theory: finer final-wave granularity cuts the end-of-kernel
// quantization tail in graph-replay timing. Kernel-side behavior untouched.

namespace {
constexpr int ROW   = 2 * 64 * 256;       // 32768  (dy=1 stride in out)
constexpr int COLS  = 256;                // dx=1 stride in out
constexpr int IMG   = 2 * 64 * ROW;       // batch stride in out
constexpr int NTHREADS_TOTAL = 16 * 64 * 64 * 2 * (256 / 4);  // 8,388,608
constexpr int THREADS = 128;
constexpr int BLOCKS  = NTHREADS_TOTAL / THREADS;             // 65536
}

__global__ void __launch_bounds__(THREADS, 16)
max_unpool_kernel(const float4* __restrict__ upd,
                  const int4*  __restrict__ mask,
                  float*       __restrict__ out)
{
    int t = blockIdx.x * THREADS + threadIdx.x;

    // t = (((b*64 + h)*64 + w)*2 + ry)*64 + c4
    int c4 = t & 63;
    int ry = (t >> 6) & 1;
    int w  = (t >> 7)  & 63;
    int h  = (t >> 13) & 63;
    int b  = t >> 19;
    int c  = c4 << 2;

    // Input group index (cell, c4): g = ((b*64+h)*64 + w)*64 + c4
    int g = ((t >> 7) << 6) | c4;

    // Window-origin flat index and this thread's row offset.
    int o00   = b * IMG + (h << 1) * ROW + (w << 1) * COLS + c;
    int sel   = ry * ROW;                 // 0 or ROW
    int obase = o00 + sel;

    float4 v = upd[g];
    int4   m = mask[g];

    // Per-lane offset within window: in {0, COLS, ROW, ROW+COLS}
    int d0 = m.x - o00;
    int d1 = m.y - o00 - 1;
    int d2 = m.z - o00 - 2;
    int d3 = m.w - o00 - 3;

    float4 rA = make_float4(d0 == sel        ? v.x : 0.f,
                            d1 == sel        ? v.y : 0.f,
                            d2 == sel        ? v.z : 0.f,
                            d3 == sel        ? v.w : 0.f);
    float4 rB = make_float4(d0 == sel + COLS ? v.x : 0.f,
                            d1 == sel + COLS ? v.y : 0.f,
                            d2 == sel + COLS ? v.z : 0.f,
                            d3 == sel + COLS ? v.w : 0.f);

    *reinterpret_cast<float4*>(out + obase)        = rA;
    *reinterpret_cast<float4*>(out + obase + COLS) = rB;
}

extern "C" void kernel_launch(void* const* d_in, const int* in_sizes, int n_in,
                              void* d_out, int out_size)
{
    const float4* upd  = reinterpret_cast<const float4*>(d_in[0]);
    const int4*   mask = reinterpret_cast<const int4*>(d_in[1]);
    float*        out  = reinterpret_cast<float*>(d_out);

    max_unpool_kernel<<<BLOCKS, THREADS>>>(upd, mask, out);
}

// round 15
// speedup vs baseline: 1.0197x; 1.0197x over previous
#include <cuda_runtime.h>
#include <cstdint>

// MaxUnpooling2D: updates [16,64,64,256] f32, mask [16,64,64,256] i32 (flat idx
// into [16,128,128,256]), out [16,128,128,256] f32.
//
// FINAL — row-split scatter, 256 threads x 32768 blocks (the twice-best-
// scoring configuration: 63.68 / 64.00us harness, 59.07us kernel, DRAM 71.7%).
//
// Each pooled cell targets exactly one slot of its private 2x2 window -> no
// duplicate indices -> plain stores; zero-fill fused (thread writes both
// positions of one window ROW for its 4 channels, update in its slot, 0.0
// elsewhere). One thread = 4 channels x 1 window row (ry in {0,1}):
// 2x16B loads + 2x16B stores 1KB apart in a single output row; every warp
// access is a fully coalesced 512B transaction and each warp's stores stay
// within one output row. Sibling-row duplicate input reads hit L1/L2
// (verified: DRAM read traffic unchanged vs depth-1).
//
// Session ledger (kernel plateau 59.1-60.0us = ~6.5 TB/s goodput on the
// irreducible 384MB; output is poisoned so all 256MB must be written):
//   gather dataflow: -11us regress; per-thread depth/pipelining: regress;
//   cache hints (.cs/.nc): neutral; 256-bit accesses: neutral;
//   block 512: neutral; block 128 (finer grid): slightly worse harness.
//   32768x256 grid: best harness tail across all samples.

namespace {
constexpr int ROW   = 2 * 64 * 256;       // 32768  (dy=1 stride in out)
constexpr int COLS  = 256;                // dx=1 stride in out
constexpr int IMG   = 2 * 64 * ROW;       // batch stride in out
constexpr int NTHREADS_TOTAL = 16 * 64 * 64 * 2 * (256 / 4);  // 8,388,608
constexpr int THREADS = 256;
constexpr int BLOCKS  = NTHREADS_TOTAL / THREADS;             // 32768
}

__global__ void __launch_bounds__(THREADS, 8)
max_unpool_kernel(const float4* __restrict__ upd,
                  const int4*  __restrict__ mask,
                  float*       __restrict__ out)
{
    int t = blockIdx.x * THREADS + threadIdx.x;

    // t = (((b*64 + h)*64 + w)*2 + ry)*64 + c4
    int c4 = t & 63;
    int ry = (t >> 6) & 1;
    int w  = (t >> 7)  & 63;
    int h  = (t >> 13) & 63;
    int b  = t >> 19;
    int c  = c4 << 2;

    // Input group index (cell, c4): g = ((b*64+h)*64 + w)*64 + c4
    int g = ((t >> 7) << 6) | c4;

    // Window-origin flat index and this thread's row offset.
    int o00   = b * IMG + (h << 1) * ROW + (w << 1) * COLS + c;
    int sel   = ry * ROW;                 // 0 or ROW
    int obase = o00 + sel;

    float4 v = upd[g];
    int4   m = mask[g];

    // Per-lane offset within window: in {0, COLS, ROW, ROW+COLS}
    int d0 = m.x - o00;
    int d1 = m.y - o00 - 1;
    int d2 = m.z - o00 - 2;
    int d3 = m.w - o00 - 3;

    float4 rA = make_float4(d0 == sel        ? v.x : 0.f,
                            d1 == sel        ? v.y : 0.f,
                            d2 == sel        ? v.z : 0.f,
                            d3 == sel        ? v.w : 0.f);
    float4 rB = make_float4(d0 == sel + COLS ? v.x : 0.f,
                            d1 == sel + COLS ? v.y : 0.f,
                            d2 == sel + COLS ? v.z : 0.f,
                            d3 == sel + COLS ? v.w : 0.f);

    *reinterpret_cast<float4*>(out + obase)        = rA;
    *reinterpret_cast<float4*>(out + obase + COLS) = rB;
}

extern "C" void kernel_launch(void* const* d_in, const int* in_sizes, int n_in,
                              void* d_out, int out_size)
{
    const float4* upd  = reinterpret_cast<const float4*>(d_in[0]);
    const int4*   mask = reinterpret_cast<const int4*>(d_in[1]);
    float*        out  = reinterpret_cast<float*>(d_out);

    max_unpool_kernel<<<BLOCKS, THREADS>>>(upd, mask, out);
}